// round 5
// baseline (speedup 1.0000x reference)
#include <cuda_runtime.h>
#include <cuda_fp16.h>
#include <stdint.h>

#define EPSF 1e-8f

constexpr int B = 8, N = 2048, D = 384, R = 64;
constexpr int HW = 256 * 256;
constexpr int W64 = N / 32;

// Output layout (float32, concatenated in reference return order)
constexpr size_t SEG_OFF  = (size_t)B * N * D;        // 6291456
constexpr size_t LOSS_OFF = SEG_OFF + (size_t)B * HW; // 6815744
constexpr size_t C_OFF    = LOSS_OFF + 1;             // 6815745

// ---------------- device scratch (static; no allocations) ----------------
__device__ uint32_t g_adj[(size_t)B * N * W64];   // 4 MB bitmask adjacency
__device__ float    g_S  [(size_t)B * N * R];     // 4 MB soft assignments
__device__ __half   g_Ch [(size_t)B * N * R];     // 2 MB normalized Chat (fp16)
__device__ __half   g_W  [(size_t)B * N * N];     // 64 MB dense normalized W (fp16)
__device__ __half   g_xT [(size_t)B * D * N];     // 12.6 MB x transposed (fp16)
__device__ float4   g_kn4[(D / 4) * R];
__device__ float    g_mask[B * N];
__device__ float    g_f  [B * R];
__device__ float    g_kl [B * N];
__device__ int      g_is64;

// ---------------- helpers ----------------
__device__ __forceinline__ float warpSum(float v) {
    #pragma unroll
    for (int o = 16; o; o >>= 1) v += __shfl_xor_sync(0xffffffffu, v, o);
    return v;
}
__device__ __forceinline__ float warpMax(float v) {
    #pragma unroll
    for (int o = 16; o; o >>= 1) v = fmaxf(v, __shfl_xor_sync(0xffffffffu, v, o));
    return v;
}
__device__ __forceinline__ int seg_at(const void* seg, int idx, int is64) {
    if (is64) return (int)((const long long*)seg)[idx];
    return ((const int*)seg)[idx];
}

// ================= small kernels =================
__global__ void k_detect(const unsigned int* __restrict__ seg) {
    if (blockIdx.x == 0 && threadIdx.x == 0) {
        unsigned int acc = 0;
        for (int i = 0; i < 128; i++) acc |= seg[2 * i + 1];
        g_is64 = (acc == 0u) ? 1 : 0;
    }
}

__global__ void k_init() {
    int idx = blockIdx.x * blockDim.x + threadIdx.x;  // B*N*W64
    int row = idx >> 6, w = idx & 63, n = row & (N - 1);
    g_adj[idx] = (w == (n >> 5)) ? (1u << (n & 31)) : 0u;
    if (idx < B * N) g_mask[idx] = 0.0f;
    if (idx < B * R) g_f[idx] = 0.0f;
}

__global__ void k_adj(const void* __restrict__ seg) {
    int idx = blockIdx.x * blockDim.x + threadIdx.x;
    if (idx >= B * HW) return;
    int is64 = g_is64;
    int b = idx >> 16, p = idx & 65535;
    int yy = p >> 8, xx = p & 255;
    int s = seg_at(seg, idx, is64);
    g_mask[b * N + s] = 1.0f;
    if (xx < 255) {
        int t = seg_at(seg, idx + 1, is64);
        if (s != t && s != 0 && t != 0) {
            atomicOr(&g_adj[((size_t)(b * N + s) << 6) + (t >> 5)], 1u << (t & 31));
            atomicOr(&g_adj[((size_t)(b * N + t) << 6) + (s >> 5)], 1u << (s & 31));
        }
    }
    if (yy < 255) {
        int t = seg_at(seg, idx + 256, is64);
        if (s != t && s != 0 && t != 0) {
            atomicOr(&g_adj[((size_t)(b * N + s) << 6) + (t >> 5)], 1u << (t & 31));
            atomicOr(&g_adj[((size_t)(b * N + t) << 6) + (s >> 5)], 1u << (s & 31));
        }
    }
}

__global__ void k_kn(const float* __restrict__ protos) {
    int r = blockIdx.x, tid = threadIdx.x;
    __shared__ float red[4];
    float ss = 0.f;
    for (int k = tid; k < D; k += 128) { float v = protos[r * D + k]; ss += v * v; }
    ss = warpSum(ss);
    if ((tid & 31) == 0) red[tid >> 5] = ss;
    __syncthreads();
    float inv = 1.0f / fmaxf(sqrtf(red[0] + red[1] + red[2] + red[3]), EPSF);
    for (int k4 = tid; k4 < D / 4; k4 += 128) {
        float4 v;
        v.x = protos[r * D + 4 * k4 + 0] * inv;
        v.y = protos[r * D + 4 * k4 + 1] * inv;
        v.z = protos[r * D + 4 * k4 + 2] * inv;
        v.w = protos[r * D + 4 * k4 + 3] * inv;
        g_kn4[k4 * R + r] = v;
    }
}

// x[b][n][d] -> g_xT[b][d][n] fp16
__global__ void k_xT(const float* __restrict__ x) {
    __shared__ float ts[32][33];
    int b = blockIdx.z, ntile = blockIdx.x, dtile = blockIdx.y;
    int tx = threadIdx.x, ty = threadIdx.y;  // 32 x 8
    #pragma unroll
    for (int i = 0; i < 4; i++) {
        int n = ntile * 32 + ty + 8 * i;
        ts[ty + 8 * i][tx] = x[((size_t)(b * N + n)) * D + dtile * 32 + tx];
    }
    __syncthreads();
    #pragma unroll
    for (int i = 0; i < 4; i++) {
        int d = dtile * 32 + ty + 8 * i;
        g_xT[((size_t)(b * D + d)) * N + ntile * 32 + tx] = __float2half_rn(ts[tx][ty + 8 * i]);
    }
}

__global__ void __launch_bounds__(64) k_S(const float* __restrict__ x) {
    int row = blockIdx.x, tid = threadIdx.x;
    __shared__ float4 xs[D / 4];
    __shared__ float red[2], red2[2];
    float ss = 0.f;
    const float4* xr = (const float4*)(x + (size_t)row * D);
    for (int k4 = tid; k4 < D / 4; k4 += 64) {
        float4 v = xr[k4];
        xs[k4] = v;
        ss += v.x * v.x + v.y * v.y + v.z * v.z + v.w * v.w;
    }
    ss = warpSum(ss);
    if ((tid & 31) == 0) red[tid >> 5] = ss;
    __syncthreads();
    float inv = 1.0f / fmaxf(sqrtf(red[0] + red[1]), EPSF);
    float dot = 0.f;
    #pragma unroll 4
    for (int k4 = 0; k4 < D / 4; k4++) {
        float4 v = xs[k4];
        float4 w = g_kn4[k4 * R + tid];
        dot += v.x * w.x + v.y * w.y + v.z * w.z + v.w * w.w;
    }
    float csim = (dot * inv + 1.0f) * 0.5f;
    float s = warpSum(csim);
    if ((tid & 31) == 0) red2[tid >> 5] = s;
    __syncthreads();
    g_S[(size_t)row * R + tid] = csim / (red2[0] + red2[1]);
}

__global__ void k_f() {
    int br = blockIdx.x;
    int b = br >> 6, r = br & 63;
    int tid = threadIdx.x;
    float acc = 0.f;
    for (int n = tid; n < N; n += 256)
        acc += g_S[((size_t)(b * N + n)) * R + r];
    acc = warpSum(acc);
    __shared__ float red[8];
    if ((tid & 31) == 0) red[tid >> 5] = acc;
    __syncthreads();
    if (tid == 0) {
        float t = 0.f;
        #pragma unroll
        for (int i = 0; i < 8; i++) t += red[i];
        g_f[br] = t;
    }
}

__global__ void k_C(float* __restrict__ outC) {
    int gw = (blockIdx.x * blockDim.x + threadIdx.x) >> 5;
    if (gw >= B * N) return;
    int lane = threadIdx.x & 31;
    int row = gw, b = row >> 11;
    const float* Sr = &g_S[(size_t)row * R];
    float s0 = Sr[lane], s1 = Sr[lane + 32];
    float f0 = g_f[b * R + lane], f1 = g_f[b * R + lane + 32];
    float p0 = s0 * s0 / (f0 + EPSF), p1 = s1 * s1 / (f1 + EPSF);
    float ps = warpSum(p0 + p1);
    p0 /= (ps + EPSF); p1 /= (ps + EPSF);
    float kl = p0 * (logf(p0 + EPSF) - logf(s0 + EPSF))
             + p1 * (logf(p1 + EPSF) - logf(s1 + EPSF));
    kl = warpSum(kl);
    float mx = warpMax(fmaxf(s0, s1));
    float e0 = expf(s0 - mx), e1 = expf(s1 - mx);
    float es = warpSum(e0 + e1);
    float c0 = e0 / es, c1 = e1 / es;
    outC[(size_t)row * R + lane] = c0;
    outC[(size_t)row * R + lane + 32] = c1;
    float nrm = warpSum(c0 * c0 + c1 * c1);
    float invn = rsqrtf(nrm);
    g_Ch[(size_t)row * R + lane]      = __float2half_rn(c0 * invn);
    g_Ch[(size_t)row * R + lane + 32] = __float2half_rn(c1 * invn);
    if (lane == 0) g_kl[row] = kl * g_mask[row];
}

__global__ void k_loss(float* __restrict__ outLoss) {
    int tid = threadIdx.x;
    float a = 0.f, mm = 0.f;
    for (int i = tid; i < B * N; i += 256) { a += g_kl[i]; mm += g_mask[i]; }
    a = warpSum(a); mm = warpSum(mm);
    __shared__ float ra[8], rm[8];
    if ((tid & 31) == 0) { ra[tid >> 5] = a; rm[tid >> 5] = mm; }
    __syncthreads();
    if (tid == 0) {
        float A = 0.f, M = 0.f;
        #pragma unroll
        for (int i = 0; i < 8; i++) { A += ra[i]; M += rm[i]; }
        *outLoss = A / (M + EPSF);
    }
}

__global__ void k_seg(const void* __restrict__ seg, float* __restrict__ outSeg) {
    int i = blockIdx.x * blockDim.x + threadIdx.x;
    if (i < B * HW) outSeg[i] = (float)seg_at(seg, i, g_is64);
}

// ================= k_wrow: dense normalized W rows (fp16) =================
__global__ void __launch_bounds__(256) k_wrow() {
    __shared__ __half wrow[8][N];   // 32 KB
    int wid = threadIdx.x >> 5, lane = threadIdx.x & 31;
    int grow = blockIdx.x * 8 + wid;          // global row b*N+n
    int brow0 = (grow >> 11) << 11;           // batch base row
    int o = lane >> 3, ol = lane & 7;

    uint4 z = make_uint4(0, 0, 0, 0);
    uint4* wr4 = (uint4*)wrow[wid];
    #pragma unroll
    for (int j = 0; j < 8; j++) wr4[lane + 32 * j] = z;
    __syncwarp();

    uint4 cn = *(const uint4*)((const char*)(g_Ch + (size_t)grow * R) + (ol << 4));
    const __half2* cn2 = (const __half2*)&cn;

    const uint32_t* adjrow = g_adj + ((size_t)grow << 6);
    float rowsum = 0.f;

    for (int w = 0; w < W64; w++) {
        uint32_t bits = adjrow[w];
        while (bits) {
            uint32_t t = bits;
            int mq[4]; int cnt = 0;
            #pragma unroll
            for (int q = 0; q < 4; q++) {
                if (t) { mq[q] = __ffs(t) - 1; t &= t - 1; cnt++; }
                else   { mq[q] = mq[0]; }
            }
            bits = t;
            int sel = mq[o < cnt ? o : 0];
            int m = (w << 5) + sel;

            uint4 cm = *(const uint4*)((const char*)(g_Ch + ((size_t)(brow0 + m)) * R) + (ol << 4));
            const __half2* cm2 = (const __half2*)&cm;
            float acc = 0.f;
            #pragma unroll
            for (int i = 0; i < 4; i++) {
                float2 fa = __half22float2(cn2[i]);
                float2 fb = __half22float2(cm2[i]);
                acc += fa.x * fb.x + fa.y * fb.y;
            }
            #pragma unroll
            for (int off = 1; off <= 4; off <<= 1)
                acc += __shfl_xor_sync(0xffffffffu, acc, off);

            float w0 = __shfl_sync(0xffffffffu, acc, 0);
            float w1 = __shfl_sync(0xffffffffu, acc, 8);
            float w2 = __shfl_sync(0xffffffffu, acc, 16);
            float w3 = __shfl_sync(0xffffffffu, acc, 24);
            rowsum += w0;
            if (cnt > 1) rowsum += w1;
            if (cnt > 2) rowsum += w2;
            if (cnt > 3) rowsum += w3;
            if (ol == 0 && o < cnt) wrow[wid][m] = __float2half_rn(acc);
        }
    }
    __syncwarp();

    float inv = 1.0f / (rowsum + EPSF);
    __half* gW = g_W + (size_t)grow * N;
    #pragma unroll
    for (int j = 0; j < 8; j++) {
        int idx = lane + 32 * j;
        uint4 v = wr4[idx];
        __half2* h = (__half2*)&v;
        #pragma unroll
        for (int i = 0; i < 4; i++) {
            float2 f = __half22float2(h[i]);
            h[i] = __float22half2_rn(make_float2(f.x * inv, f.y * inv));
        }
        ((uint4*)gW)[idx] = v;
    }
}

// ================= k_gemm: out = W @ x via mma.sync (HMMA) =================
// CTA tile 128(M=n) x 128(N=d), K=2048 in chunks of 64. 256 threads, 8 warps 2x4.
// smem: A/B tiles 128 rows x 64 halves, padded to LDK=72 halves (conflict-free).
constexpr int LDK = 72;
constexpr int TILE_BYTES = 128 * LDK * 2;         // 18432
constexpr int GEMM_SMEM = 4 * TILE_BYTES;         // A0,B0,A1,B1 = 73728

__device__ __forceinline__ void mma16816(float* c, uint32_t a0, uint32_t a1,
                                         uint32_t a2, uint32_t a3,
                                         uint32_t b0, uint32_t b1) {
    asm volatile(
        "mma.sync.aligned.m16n8k16.row.col.f32.f16.f16.f32 "
        "{%0,%1,%2,%3}, {%4,%5,%6,%7}, {%8,%9}, {%0,%1,%2,%3};\n"
        : "+f"(c[0]), "+f"(c[1]), "+f"(c[2]), "+f"(c[3])
        : "r"(a0), "r"(a1), "r"(a2), "r"(a3), "r"(b0), "r"(b1));
}

__global__ void __launch_bounds__(256, 1) k_gemm(float* __restrict__ out) {
    extern __shared__ char smem[];
    int tid = threadIdx.x;
    int wid = tid >> 5, lane = tid & 31;
    int gid = lane >> 2, tid4 = lane & 3;
    int mw = wid >> 2, nw = wid & 3;          // 2 x 4 warp grid

    int bid = blockIdx.x;
    int nt = bid % 3, mt = (bid / 3) & 15, b = bid / 48;
    int n0 = mt * 128, d0 = nt * 128;
    const __half* Ab = g_W  + ((size_t)(b * N) + n0) * N;   // [128][2048] K-major
    const __half* Bb = g_xT + ((size_t)(b * D) + d0) * N;   // [128][2048] K-major

    int rrow = tid >> 3;            // 0..31
    int rcol = (tid & 7) * 8;       // halves

    float acc[4][4][4];
    #pragma unroll
    for (int mi = 0; mi < 4; mi++)
        #pragma unroll
        for (int ni = 0; ni < 4; ni++)
            #pragma unroll
            for (int q = 0; q < 4; q++) acc[mi][ni][q] = 0.f;

    uint4 rA[4], rB[4];
    auto ldg = [&](int c) {
        #pragma unroll
        for (int j = 0; j < 4; j++) {
            int row = j * 32 + rrow;
            rA[j] = *(const uint4*)(Ab + (size_t)row * N + c * 64 + rcol);
            rB[j] = *(const uint4*)(Bb + (size_t)row * N + c * 64 + rcol);
        }
    };
    auto sts = [&](int buf) {
        __half* dA = (__half*)(smem + buf * 2 * TILE_BYTES);
        __half* dB = (__half*)(smem + buf * 2 * TILE_BYTES + TILE_BYTES);
        #pragma unroll
        for (int j = 0; j < 4; j++) {
            int row = j * 32 + rrow;
            *(uint4*)(dA + row * LDK + rcol) = rA[j];
            *(uint4*)(dB + row * LDK + rcol) = rB[j];
        }
    };

    ldg(0);
    sts(0);
    __syncthreads();

    for (int c = 0; c < 32; c++) {
        if (c < 31) ldg(c + 1);
        const __half* sA = (const __half*)(smem + (c & 1) * 2 * TILE_BYTES);
        const __half* sB = (const __half*)(smem + (c & 1) * 2 * TILE_BYTES + TILE_BYTES);
        #pragma unroll
        for (int ks = 0; ks < 4; ks++) {
            int k0 = ks * 16 + tid4 * 2;
            uint32_t bf[4][2];
            #pragma unroll
            for (int ni = 0; ni < 4; ni++) {
                const uint32_t* bp =
                    (const uint32_t*)(sB + (nw * 32 + ni * 8 + gid) * LDK + k0);
                bf[ni][0] = bp[0];
                bf[ni][1] = bp[4];   // +8 halves
            }
            #pragma unroll
            for (int mi = 0; mi < 4; mi++) {
                const uint32_t* ap0 =
                    (const uint32_t*)(sA + (mw * 64 + mi * 16 + gid) * LDK + k0);
                const uint32_t* ap1 = ap0 + (8 * LDK) / 2;  // row +8
                uint32_t a0 = ap0[0], a2 = ap0[4];
                uint32_t a1 = ap1[0], a3 = ap1[4];
                #pragma unroll
                for (int ni = 0; ni < 4; ni++)
                    mma16816(acc[mi][ni], a0, a1, a2, a3, bf[ni][0], bf[ni][1]);
            }
        }
        if (c < 31) {
            __syncthreads();
            sts((c + 1) & 1);
            __syncthreads();
        }
    }

    // epilogue: write fp32 directly
    #pragma unroll
    for (int mi = 0; mi < 4; mi++) {
        int m = n0 + mw * 64 + mi * 16 + gid;
        float* base = out + ((size_t)(b * N) + m) * D + d0;
        #pragma unroll
        for (int ni = 0; ni < 4; ni++) {
            int dcol = nw * 32 + ni * 8 + tid4 * 2;
            float2 lo = make_float2(acc[mi][ni][0], acc[mi][ni][1]);
            float2 hi = make_float2(acc[mi][ni][2], acc[mi][ni][3]);
            *(float2*)(base + dcol) = lo;
            *(float2*)(base + 8 * D + dcol) = hi;
        }
    }
}

// ---------------- launch ----------------
extern "C" void kernel_launch(void* const* d_in, const int* in_sizes, int n_in,
                              void* d_out, int out_size) {
    const float* x      = (const float*)d_in[0];
    const void*  seg    = d_in[1];
    const float* protos = (const float*)d_in[2];
    float* out = (float*)d_out;

    float* outSeg  = out + SEG_OFF;
    float* outLoss = out + LOSS_OFF;
    float* outC    = out + C_OFF;

    static int smem_set = 0;
    if (!smem_set) {
        cudaFuncSetAttribute(k_gemm, cudaFuncAttributeMaxDynamicSharedMemorySize,
                             GEMM_SMEM);
        smem_set = 1;
    }

    k_detect<<<1, 32>>>((const unsigned int*)seg);
    k_init<<<(B * N * W64) / 256, 256>>>();
    k_adj<<<(B * HW) / 256, 256>>>(seg);
    k_kn<<<R, 128>>>(protos);
    k_xT<<<dim3(N / 32, D / 32, B), dim3(32, 8)>>>(x);
    k_S<<<B * N, 64>>>(x);
    k_f<<<B * R, 256>>>();
    k_C<<<(B * N) / 4, 128>>>(outC);
    k_loss<<<1, 256>>>(outLoss);
    k_seg<<<(B * HW) / 256, 256>>>(seg, outSeg);
    k_wrow<<<(B * N) / 8, 256>>>();
    k_gemm<<<B * 16 * 3, 256, GEMM_SMEM>>>(out);
}

// round 6
// speedup vs baseline: 1.1214x; 1.1214x over previous
#include <cuda_runtime.h>
#include <cuda_fp16.h>
#include <stdint.h>

#define EPSF 1e-8f

constexpr int B = 8, N = 2048, D = 384, R = 64;
constexpr int HW = 256 * 256;
constexpr int W64 = N / 32;

// Output layout (float32, concatenated in reference return order)
constexpr size_t SEG_OFF  = (size_t)B * N * D;        // 6291456
constexpr size_t LOSS_OFF = SEG_OFF + (size_t)B * HW; // 6815744
constexpr size_t C_OFF    = LOSS_OFF + 1;             // 6815745

// ---------------- device scratch ----------------
__device__ uint32_t g_adj[(size_t)B * N * W64];   // 4 MB bitmask adjacency
__device__ float    g_S  [(size_t)B * N * R];     // 4 MB
__device__ __half   g_Ch [(size_t)B * N * R];     // 2 MB normalized Chat fp16
__device__ __half   g_W  [(size_t)B * N * N];     // 64 MB dense normalized W fp16
__device__ __half   g_xT [(size_t)B * D * N];     // 12.6 MB x^T fp16
__device__ float    g_rowinv[B * N];
__device__ float4   g_kn4[(D / 4) * R];
__device__ float    g_mask[B * N];
__device__ float    g_f  [B * R];
__device__ float    g_kl [B * N];
__device__ int      g_is64;

// ---------------- helpers ----------------
__device__ __forceinline__ float warpSum(float v) {
    #pragma unroll
    for (int o = 16; o; o >>= 1) v += __shfl_xor_sync(0xffffffffu, v, o);
    return v;
}
__device__ __forceinline__ float warpMax(float v) {
    #pragma unroll
    for (int o = 16; o; o >>= 1) v = fmaxf(v, __shfl_xor_sync(0xffffffffu, v, o));
    return v;
}
__device__ __forceinline__ int seg_at(const void* seg, int idx, int is64) {
    if (is64) return (int)((const long long*)seg)[idx];
    return ((const int*)seg)[idx];
}
__device__ __forceinline__ uint32_t smem_u32(const void* p) {
    uint32_t a;
    asm("{ .reg .u64 t; cvta.to.shared.u64 t, %1; cvt.u32.u64 %0, t; }" : "=r"(a) : "l"(p));
    return a;
}
__device__ __forceinline__ void cp16(uint32_t saddr, const void* g) {
    asm volatile("cp.async.cg.shared.global [%0], [%1], 16;" :: "r"(saddr), "l"(g));
}
#define CP_COMMIT() asm volatile("cp.async.commit_group;" ::: "memory")
#define CP_WAIT(n)  asm volatile("cp.async.wait_group %0;" :: "n"(n) : "memory")

__device__ __forceinline__ void mma16816(float* c, uint32_t a0, uint32_t a1,
                                         uint32_t a2, uint32_t a3,
                                         uint32_t b0, uint32_t b1) {
    asm volatile(
        "mma.sync.aligned.m16n8k16.row.col.f32.f16.f16.f32 "
        "{%0,%1,%2,%3}, {%4,%5,%6,%7}, {%8,%9}, {%0,%1,%2,%3};\n"
        : "+f"(c[0]), "+f"(c[1]), "+f"(c[2]), "+f"(c[3])
        : "r"(a0), "r"(a1), "r"(a2), "r"(a3), "r"(b0), "r"(b1));
}

// ================= small kernels =================
__global__ void k_detect(const unsigned int* __restrict__ seg) {
    if (blockIdx.x == 0 && threadIdx.x == 0) {
        unsigned int acc = 0;
        for (int i = 0; i < 128; i++) acc |= seg[2 * i + 1];
        g_is64 = (acc == 0u) ? 1 : 0;
    }
}

__global__ void k_init() {
    int idx = blockIdx.x * blockDim.x + threadIdx.x;  // B*N*W64
    int row = idx >> 6, w = idx & 63, n = row & (N - 1);
    g_adj[idx] = (w == (n >> 5)) ? (1u << (n & 31)) : 0u;
    if (idx < B * N) g_mask[idx] = 0.0f;
    if (idx < B * R) g_f[idx] = 0.0f;
}

__global__ void k_adj(const void* __restrict__ seg) {
    int idx = blockIdx.x * blockDim.x + threadIdx.x;
    if (idx >= B * HW) return;
    int is64 = g_is64;
    int b = idx >> 16, p = idx & 65535;
    int yy = p >> 8, xx = p & 255;
    int s = seg_at(seg, idx, is64);
    g_mask[b * N + s] = 1.0f;
    if (xx < 255) {
        int t = seg_at(seg, idx + 1, is64);
        if (s != t && s != 0 && t != 0) {
            atomicOr(&g_adj[((size_t)(b * N + s) << 6) + (t >> 5)], 1u << (t & 31));
            atomicOr(&g_adj[((size_t)(b * N + t) << 6) + (s >> 5)], 1u << (s & 31));
        }
    }
    if (yy < 255) {
        int t = seg_at(seg, idx + 256, is64);
        if (s != t && s != 0 && t != 0) {
            atomicOr(&g_adj[((size_t)(b * N + s) << 6) + (t >> 5)], 1u << (t & 31));
            atomicOr(&g_adj[((size_t)(b * N + t) << 6) + (s >> 5)], 1u << (s & 31));
        }
    }
}

__global__ void k_kn(const float* __restrict__ protos) {
    int r = blockIdx.x, tid = threadIdx.x;
    __shared__ float red[4];
    float ss = 0.f;
    for (int k = tid; k < D; k += 128) { float v = protos[r * D + k]; ss += v * v; }
    ss = warpSum(ss);
    if ((tid & 31) == 0) red[tid >> 5] = ss;
    __syncthreads();
    float inv = 1.0f / fmaxf(sqrtf(red[0] + red[1] + red[2] + red[3]), EPSF);
    for (int k4 = tid; k4 < D / 4; k4 += 128) {
        float4 v;
        v.x = protos[r * D + 4 * k4 + 0] * inv;
        v.y = protos[r * D + 4 * k4 + 1] * inv;
        v.z = protos[r * D + 4 * k4 + 2] * inv;
        v.w = protos[r * D + 4 * k4 + 3] * inv;
        g_kn4[k4 * R + r] = v;
    }
}

// x[b][n][d] -> g_xT[b][d][n] fp16
__global__ void k_xT(const float* __restrict__ x) {
    __shared__ float ts[32][33];
    int b = blockIdx.z, ntile = blockIdx.x, dtile = blockIdx.y;
    int tx = threadIdx.x, ty = threadIdx.y;  // 32 x 8
    #pragma unroll
    for (int i = 0; i < 4; i++) {
        int n = ntile * 32 + ty + 8 * i;
        ts[ty + 8 * i][tx] = x[((size_t)(b * N + n)) * D + dtile * 32 + tx];
    }
    __syncthreads();
    #pragma unroll
    for (int i = 0; i < 4; i++) {
        int d = dtile * 32 + ty + 8 * i;
        g_xT[((size_t)(b * D + d)) * N + ntile * 32 + tx] = __float2half_rn(ts[tx][ty + 8 * i]);
    }
}

__global__ void __launch_bounds__(64) k_S(const float* __restrict__ x) {
    int row = blockIdx.x, tid = threadIdx.x;
    __shared__ float4 xs[D / 4];
    __shared__ float red[2], red2[2];
    float ss = 0.f;
    const float4* xr = (const float4*)(x + (size_t)row * D);
    for (int k4 = tid; k4 < D / 4; k4 += 64) {
        float4 v = xr[k4];
        xs[k4] = v;
        ss += v.x * v.x + v.y * v.y + v.z * v.z + v.w * v.w;
    }
    ss = warpSum(ss);
    if ((tid & 31) == 0) red[tid >> 5] = ss;
    __syncthreads();
    float inv = 1.0f / fmaxf(sqrtf(red[0] + red[1]), EPSF);
    float dot = 0.f;
    #pragma unroll 4
    for (int k4 = 0; k4 < D / 4; k4++) {
        float4 v = xs[k4];
        float4 w = g_kn4[k4 * R + tid];
        dot += v.x * w.x + v.y * w.y + v.z * w.z + v.w * w.w;
    }
    float csim = (dot * inv + 1.0f) * 0.5f;
    float s = warpSum(csim);
    if ((tid & 31) == 0) red2[tid >> 5] = s;
    __syncthreads();
    g_S[(size_t)row * R + tid] = csim / (red2[0] + red2[1]);
}

__global__ void k_f() {
    int br = blockIdx.x;
    int b = br >> 6, r = br & 63;
    int tid = threadIdx.x;
    float acc = 0.f;
    for (int n = tid; n < N; n += 256)
        acc += g_S[((size_t)(b * N + n)) * R + r];
    acc = warpSum(acc);
    __shared__ float red[8];
    if ((tid & 31) == 0) red[tid >> 5] = acc;
    __syncthreads();
    if (tid == 0) {
        float t = 0.f;
        #pragma unroll
        for (int i = 0; i < 8; i++) t += red[i];
        g_f[br] = t;
    }
}

__global__ void k_C(float* __restrict__ outC) {
    int gw = (blockIdx.x * blockDim.x + threadIdx.x) >> 5;
    if (gw >= B * N) return;
    int lane = threadIdx.x & 31;
    int row = gw, b = row >> 11;
    const float* Sr = &g_S[(size_t)row * R];
    float s0 = Sr[lane], s1 = Sr[lane + 32];
    float f0 = g_f[b * R + lane], f1 = g_f[b * R + lane + 32];
    float p0 = s0 * s0 / (f0 + EPSF), p1 = s1 * s1 / (f1 + EPSF);
    float ps = warpSum(p0 + p1);
    p0 /= (ps + EPSF); p1 /= (ps + EPSF);
    float kl = p0 * (logf(p0 + EPSF) - logf(s0 + EPSF))
             + p1 * (logf(p1 + EPSF) - logf(s1 + EPSF));
    kl = warpSum(kl);
    float mx = warpMax(fmaxf(s0, s1));
    float e0 = expf(s0 - mx), e1 = expf(s1 - mx);
    float es = warpSum(e0 + e1);
    float c0 = e0 / es, c1 = e1 / es;
    outC[(size_t)row * R + lane] = c0;
    outC[(size_t)row * R + lane + 32] = c1;
    float nrm = warpSum(c0 * c0 + c1 * c1);
    float invn = rsqrtf(nrm);
    g_Ch[(size_t)row * R + lane]      = __float2half_rn(c0 * invn);
    g_Ch[(size_t)row * R + lane + 32] = __float2half_rn(c1 * invn);
    if (lane == 0) g_kl[row] = kl * g_mask[row];
}

__global__ void k_loss(float* __restrict__ outLoss) {
    int tid = threadIdx.x;
    float a = 0.f, mm = 0.f;
    for (int i = tid; i < B * N; i += 256) { a += g_kl[i]; mm += g_mask[i]; }
    a = warpSum(a); mm = warpSum(mm);
    __shared__ float ra[8], rm[8];
    if ((tid & 31) == 0) { ra[tid >> 5] = a; rm[tid >> 5] = mm; }
    __syncthreads();
    if (tid == 0) {
        float A = 0.f, M = 0.f;
        #pragma unroll
        for (int i = 0; i < 8; i++) { A += ra[i]; M += rm[i]; }
        *outLoss = A / (M + EPSF);
    }
}

__global__ void k_seg(const void* __restrict__ seg, float* __restrict__ outSeg) {
    int i = blockIdx.x * blockDim.x + threadIdx.x;
    if (i < B * HW) outSeg[i] = (float)seg_at(seg, i, g_is64);
}

// ================= k_rowsum: rowinv via T_n = sum_{m in nbr} Chat_m =================
__global__ void __launch_bounds__(256) k_rowsum() {
    int wid = threadIdx.x >> 5, lane = threadIdx.x & 31;
    int row = blockIdx.x * 8 + wid;           // b*N+n
    int brow0 = (row >> 11) << 11;
    const uint32_t* adjrow = g_adj + ((size_t)row << 6);
    float2 T = make_float2(0.f, 0.f);
    for (int wi = 0; wi < W64; wi++) {
        uint32_t bits = adjrow[wi];
        while (bits) {
            int m = (wi << 5) + (__ffs(bits) - 1);
            bits &= bits - 1;
            __half2 v = ((const __half2*)(g_Ch + (size_t)(brow0 + m) * R))[lane];
            float2 f = __half22float2(v);
            T.x += f.x; T.y += f.y;
        }
    }
    float2 cn = __half22float2(((const __half2*)(g_Ch + (size_t)row * R))[lane]);
    float s = warpSum(cn.x * T.x + cn.y * T.y);
    if (lane == 0) g_rowinv[row] = 1.0f / (s + EPSF);
}

// ================= k_wgemm: W = mask o (Chat Chat^T) * rowinv, fp16 =================
// CTA tile 128(rows n) x 128(cols m), K = 64. 256 threads, 8 warps 2x4, warp 64x32.
constexpr int WLDK = 72;
__global__ void __launch_bounds__(256) k_wgemm() {
    __shared__ __half sA[128 * WLDK];   // 18432 B
    __shared__ __half sB[128 * WLDK];
    __shared__ uint32_t sadj[128 * 4];
    __shared__ float sinv[128];

    int tid = threadIdx.x, wid = tid >> 5, lane = tid & 31;
    int gid = lane >> 2, tid4 = lane & 3;
    int mw = wid >> 2, nw = wid & 3;
    int bid = blockIdx.x;
    int mt = bid & 15, nt = (bid >> 4) & 15, b = bid >> 8;
    int n0 = nt * 128, m0 = mt * 128;

    // load Ch tiles (rows n0.. / m0..), 64 halves per row padded to 72
    #pragma unroll
    for (int j = 0; j < 8; j++) {
        int idx = tid + 256 * j;           // 0..2047
        int row = idx >> 3, seg = idx & 7; // row 0..255
        const __half* src = g_Ch + (size_t)(b * N + (row < 128 ? n0 + row : m0 + row - 128)) * R + seg * 8;
        __half* dst = (row < 128 ? sA + row * WLDK : sB + (row - 128) * WLDK) + seg * 8;
        *(uint4*)dst = *(const uint4*)src;
    }
    if (tid < 128) sinv[tid] = g_rowinv[b * N + n0 + tid];
    #pragma unroll
    for (int j = 0; j < 2; j++) {
        int idx = tid + 256 * j;           // 0..511
        sadj[idx] = g_adj[((size_t)(b * N + n0 + (idx >> 2)) << 6) + (m0 >> 5) + (idx & 3)];
    }
    __syncthreads();

    float acc[4][4][4];
    #pragma unroll
    for (int mi = 0; mi < 4; mi++)
        #pragma unroll
        for (int ni = 0; ni < 4; ni++)
            #pragma unroll
            for (int q = 0; q < 4; q++) acc[mi][ni][q] = 0.f;

    #pragma unroll
    for (int ks = 0; ks < 4; ks++) {
        int k0 = ks * 16 + tid4 * 2;
        uint32_t bf[4][2];
        #pragma unroll
        for (int ni = 0; ni < 4; ni++) {
            const __half* bp = sB + (nw * 32 + ni * 8 + gid) * WLDK + k0;
            bf[ni][0] = *(const uint32_t*)bp;
            bf[ni][1] = *(const uint32_t*)(bp + 8);
        }
        #pragma unroll
        for (int mi = 0; mi < 4; mi++) {
            const __half* ap = sA + (mw * 64 + mi * 16 + gid) * WLDK + k0;
            uint32_t a0 = *(const uint32_t*)ap;
            uint32_t a2 = *(const uint32_t*)(ap + 8);
            uint32_t a1 = *(const uint32_t*)(ap + 8 * WLDK);
            uint32_t a3 = *(const uint32_t*)(ap + 8 * WLDK + 8);
            #pragma unroll
            for (int ni = 0; ni < 4; ni++)
                mma16816(acc[mi][ni], a0, a1, a2, a3, bf[ni][0], bf[ni][1]);
        }
    }

    // epilogue: mask + scale + fp16 store
    #pragma unroll
    for (int mi = 0; mi < 4; mi++) {
        int r0 = mw * 64 + mi * 16 + gid;      // tile-local rows r0, r0+8
        #pragma unroll
        for (int ni = 0; ni < 4; ni++) {
            int c = nw * 32 + ni * 8 + tid4 * 2;  // tile-local col (even)
            #pragma unroll
            for (int h = 0; h < 2; h++) {
                int r = r0 + 8 * h;
                uint32_t word = sadj[r * 4 + (c >> 5)];
                float iv = sinv[r];
                float v0 = ((word >> (c & 31)) & 1u) ? acc[mi][ni][2 * h + 0] * iv : 0.f;
                float v1 = ((word >> ((c + 1) & 31)) & 1u) ? acc[mi][ni][2 * h + 1] * iv : 0.f;
                __half2 hv = __floats2half2_rn(v0, v1);
                *(__half2*)(g_W + (size_t)(b * N + n0 + r) * N + m0 + c) = hv;
            }
        }
    }
}

// ================= k_gemm: out = W @ x, 128x384 CTA tile, cp.async 3-stage =================
constexpr int GLDK = 72;                               // halves per smem row
constexpr int G_AROWS = 128, G_BROWS = 384;
constexpr int STAGE_HALVES = (G_AROWS + G_BROWS) * GLDK;  // 36864
constexpr int STAGE_BYTES = STAGE_HALVES * 2;             // 73728
constexpr int GEMM_SMEM = 3 * STAGE_BYTES;                // 221184

__global__ void __launch_bounds__(512, 1) k_gemm(float* __restrict__ out) {
    extern __shared__ char smem[];
    uint32_t sb = smem_u32(smem);
    int tid = threadIdx.x, wid = tid >> 5, lane = tid & 31;
    int gid = lane >> 2, tid4 = lane & 3;
    int mw = wid >> 2, nw = wid & 3;          // 4 x 4 warps, warp tile 32 x 96
    int bid = blockIdx.x;
    int mt = bid & 15, b = bid >> 4;
    int n0 = mt * 128;
    const __half* Ab = g_W  + (size_t)(b * N + n0) * N;  // 128 rows x K2048
    const __half* Bb = g_xT + (size_t)b * D * N;         // 384 rows x K2048

    auto issue = [&](int c) {
        uint32_t stage = sb + (c % 3) * STAGE_BYTES;
        #pragma unroll
        for (int j = 0; j < 8; j++) {
            int idx = tid + 512 * j;
            int row = idx >> 3, seg = idx & 7;   // row 0..511
            const __half* gp = (row < G_AROWS)
                ? Ab + (size_t)row * N + c * 64 + seg * 8
                : Bb + (size_t)(row - G_AROWS) * N + c * 64 + seg * 8;
            cp16(stage + row * (GLDK * 2) + seg * 16, gp);
        }
        CP_COMMIT();
    };

    float acc[2][12][4];
    #pragma unroll
    for (int mi = 0; mi < 2; mi++)
        #pragma unroll
        for (int ni = 0; ni < 12; ni++)
            #pragma unroll
            for (int q = 0; q < 4; q++) acc[mi][ni][q] = 0.f;

    issue(0);
    issue(1);

    for (int c = 0; c < 32; c++) {
        if (c + 2 < 32) { CP_WAIT(1); } else { CP_WAIT(0); }
        __syncthreads();
        if (c + 2 < 32) issue(c + 2);

        const __half* sA = (const __half*)(smem + (c % 3) * STAGE_BYTES);
        const __half* sB = sA + G_AROWS * GLDK;
        #pragma unroll
        for (int ks = 0; ks < 4; ks++) {
            int k0 = ks * 16 + tid4 * 2;
            uint32_t a[2][4];
            #pragma unroll
            for (int mi = 0; mi < 2; mi++) {
                const __half* ap = sA + (mw * 32 + mi * 16 + gid) * GLDK + k0;
                a[mi][0] = *(const uint32_t*)ap;
                a[mi][2] = *(const uint32_t*)(ap + 8);
                a[mi][1] = *(const uint32_t*)(ap + 8 * GLDK);
                a[mi][3] = *(const uint32_t*)(ap + 8 * GLDK + 8);
            }
            #pragma unroll
            for (int ni = 0; ni < 12; ni++) {
                const __half* bp = sB + (nw * 96 + ni * 8 + gid) * GLDK + k0;
                uint32_t b0 = *(const uint32_t*)bp;
                uint32_t b1 = *(const uint32_t*)(bp + 8);
                mma16816(acc[0][ni], a[0][0], a[0][1], a[0][2], a[0][3], b0, b1);
                mma16816(acc[1][ni], a[1][0], a[1][1], a[1][2], a[1][3], b0, b1);
            }
        }
        __syncthreads();
    }

    // epilogue
    #pragma unroll
    for (int mi = 0; mi < 2; mi++) {
        int m = n0 + mw * 32 + mi * 16 + gid;
        float* base = out + (size_t)(b * N + m) * D;
        #pragma unroll
        for (int ni = 0; ni < 12; ni++) {
            int d = nw * 96 + ni * 8 + tid4 * 2;
            *(float2*)(base + d) = make_float2(acc[mi][ni][0], acc[mi][ni][1]);
            *(float2*)(base + 8 * D + d) = make_float2(acc[mi][ni][2], acc[mi][ni][3]);
        }
    }
}

// ---------------- launch ----------------
extern "C" void kernel_launch(void* const* d_in, const int* in_sizes, int n_in,
                              void* d_out, int out_size) {
    const float* x      = (const float*)d_in[0];
    const void*  seg    = d_in[1];
    const float* protos = (const float*)d_in[2];
    float* out = (float*)d_out;

    float* outSeg  = out + SEG_OFF;
    float* outLoss = out + LOSS_OFF;
    float* outC    = out + C_OFF;

    cudaFuncSetAttribute(k_gemm, cudaFuncAttributeMaxDynamicSharedMemorySize, GEMM_SMEM);

    k_detect<<<1, 32>>>((const unsigned int*)seg);
    k_init<<<(B * N * W64) / 256, 256>>>();
    k_adj<<<(B * HW) / 256, 256>>>(seg);
    k_kn<<<R, 128>>>(protos);
    k_xT<<<dim3(N / 32, D / 32, B), dim3(32, 8)>>>(x);
    k_S<<<B * N, 64>>>(x);
    k_f<<<B * R, 256>>>();
    k_C<<<(B * N) / 4, 128>>>(outC);
    k_loss<<<1, 256>>>(outLoss);
    k_seg<<<(B * HW) / 256, 256>>>(seg, outSeg);
    k_rowsum<<<(B * N) / 8, 256>>>();
    k_wgemm<<<B * 16 * 16, 256>>>();
    k_gemm<<<B * 16, 512, GEMM_SMEM>>>(out);
}

// round 7
// speedup vs baseline: 1.3627x; 1.2152x over previous
#include <cuda_runtime.h>
#include <cuda_fp16.h>
#include <stdint.h>

#define EPSF 1e-8f

constexpr int B = 8, N = 2048, D = 384, R = 64;
constexpr int HW = 256 * 256;
constexpr int W64 = N / 32;

// Output layout (float32, concatenated in reference return order)
constexpr size_t SEG_OFF  = (size_t)B * N * D;        // 6291456
constexpr size_t LOSS_OFF = SEG_OFF + (size_t)B * HW; // 6815744
constexpr size_t C_OFF    = LOSS_OFF + 1;             // 6815745

// ---------------- device scratch ----------------
__device__ uint32_t g_adj[(size_t)B * N * W64];   // 4 MB bitmask adjacency
__device__ float    g_S  [(size_t)B * N * R];     // 4 MB
__device__ __half   g_Ch [(size_t)B * N * R];     // 2 MB normalized Chat fp16
__device__ __half   g_xT [(size_t)B * D * N];     // 12.6 MB x^T fp16
__device__ float4   g_kn4[(D / 4) * R];
__device__ float    g_mask[B * N];
__device__ float    g_f  [B * R];
__device__ float    g_kl [B * N];
__device__ int      g_is64;

// ---------------- helpers ----------------
__device__ __forceinline__ float warpSum(float v) {
    #pragma unroll
    for (int o = 16; o; o >>= 1) v += __shfl_xor_sync(0xffffffffu, v, o);
    return v;
}
__device__ __forceinline__ float warpMax(float v) {
    #pragma unroll
    for (int o = 16; o; o >>= 1) v = fmaxf(v, __shfl_xor_sync(0xffffffffu, v, o));
    return v;
}
__device__ __forceinline__ int seg_at(const void* seg, int idx, int is64) {
    if (is64) return (int)((const long long*)seg)[idx];
    return ((const int*)seg)[idx];
}
__device__ __forceinline__ uint32_t smem_u32(const void* p) {
    uint32_t a;
    asm("{ .reg .u64 t; cvta.to.shared.u64 t, %1; cvt.u32.u64 %0, t; }" : "=r"(a) : "l"(p));
    return a;
}
__device__ __forceinline__ void cp16(uint32_t saddr, const void* g) {
    asm volatile("cp.async.cg.shared.global [%0], [%1], 16;" :: "r"(saddr), "l"(g));
}
#define CP_COMMIT() asm volatile("cp.async.commit_group;" ::: "memory")
#define CP_WAIT(n)  asm volatile("cp.async.wait_group %0;" :: "n"(n) : "memory")

__device__ __forceinline__ void mma16816(float* c, uint32_t a0, uint32_t a1,
                                         uint32_t a2, uint32_t a3,
                                         uint32_t b0, uint32_t b1) {
    asm volatile(
        "mma.sync.aligned.m16n8k16.row.col.f32.f16.f16.f32 "
        "{%0,%1,%2,%3}, {%4,%5,%6,%7}, {%8,%9}, {%0,%1,%2,%3};\n"
        : "+f"(c[0]), "+f"(c[1]), "+f"(c[2]), "+f"(c[3])
        : "r"(a0), "r"(a1), "r"(a2), "r"(a3), "r"(b0), "r"(b1));
}

// ================= small kernels =================
__global__ void k_detect(const unsigned int* __restrict__ seg) {
    if (blockIdx.x == 0 && threadIdx.x == 0) {
        unsigned int acc = 0;
        for (int i = 0; i < 128; i++) acc |= seg[2 * i + 1];
        g_is64 = (acc == 0u) ? 1 : 0;
    }
}

__global__ void k_init() {
    int idx = blockIdx.x * blockDim.x + threadIdx.x;  // B*N*W64
    int row = idx >> 6, w = idx & 63, n = row & (N - 1);
    g_adj[idx] = (w == (n >> 5)) ? (1u << (n & 31)) : 0u;
    if (idx < B * N) g_mask[idx] = 0.0f;
    if (idx < B * R) g_f[idx] = 0.0f;
}

__global__ void k_adj(const void* __restrict__ seg) {
    int idx = blockIdx.x * blockDim.x + threadIdx.x;
    if (idx >= B * HW) return;
    int is64 = g_is64;
    int b = idx >> 16, p = idx & 65535;
    int yy = p >> 8, xx = p & 255;
    int s = seg_at(seg, idx, is64);
    g_mask[b * N + s] = 1.0f;
    if (xx < 255) {
        int t = seg_at(seg, idx + 1, is64);
        if (s != t && s != 0 && t != 0) {
            atomicOr(&g_adj[((size_t)(b * N + s) << 6) + (t >> 5)], 1u << (t & 31));
            atomicOr(&g_adj[((size_t)(b * N + t) << 6) + (s >> 5)], 1u << (s & 31));
        }
    }
    if (yy < 255) {
        int t = seg_at(seg, idx + 256, is64);
        if (s != t && s != 0 && t != 0) {
            atomicOr(&g_adj[((size_t)(b * N + s) << 6) + (t >> 5)], 1u << (t & 31));
            atomicOr(&g_adj[((size_t)(b * N + t) << 6) + (s >> 5)], 1u << (s & 31));
        }
    }
}

__global__ void k_kn(const float* __restrict__ protos) {
    int r = blockIdx.x, tid = threadIdx.x;
    __shared__ float red[4];
    float ss = 0.f;
    for (int k = tid; k < D; k += 128) { float v = protos[r * D + k]; ss += v * v; }
    ss = warpSum(ss);
    if ((tid & 31) == 0) red[tid >> 5] = ss;
    __syncthreads();
    float inv = 1.0f / fmaxf(sqrtf(red[0] + red[1] + red[2] + red[3]), EPSF);
    for (int k4 = tid; k4 < D / 4; k4 += 128) {
        float4 v;
        v.x = protos[r * D + 4 * k4 + 0] * inv;
        v.y = protos[r * D + 4 * k4 + 1] * inv;
        v.z = protos[r * D + 4 * k4 + 2] * inv;
        v.w = protos[r * D + 4 * k4 + 3] * inv;
        g_kn4[k4 * R + r] = v;
    }
}

// x[b][n][d] -> g_xT[b][d][n] fp16
__global__ void k_xT(const float* __restrict__ x) {
    __shared__ float ts[32][33];
    int b = blockIdx.z, ntile = blockIdx.x, dtile = blockIdx.y;
    int tx = threadIdx.x, ty = threadIdx.y;  // 32 x 8
    #pragma unroll
    for (int i = 0; i < 4; i++) {
        int n = ntile * 32 + ty + 8 * i;
        ts[ty + 8 * i][tx] = x[((size_t)(b * N + n)) * D + dtile * 32 + tx];
    }
    __syncthreads();
    #pragma unroll
    for (int i = 0; i < 4; i++) {
        int d = dtile * 32 + ty + 8 * i;
        g_xT[((size_t)(b * D + d)) * N + ntile * 32 + tx] = __float2half_rn(ts[tx][ty + 8 * i]);
    }
}

__global__ void __launch_bounds__(64) k_S(const float* __restrict__ x) {
    int row = blockIdx.x, tid = threadIdx.x;
    __shared__ float4 xs[D / 4];
    __shared__ float red[2], red2[2];
    float ss = 0.f;
    const float4* xr = (const float4*)(x + (size_t)row * D);
    for (int k4 = tid; k4 < D / 4; k4 += 64) {
        float4 v = xr[k4];
        xs[k4] = v;
        ss += v.x * v.x + v.y * v.y + v.z * v.z + v.w * v.w;
    }
    ss = warpSum(ss);
    if ((tid & 31) == 0) red[tid >> 5] = ss;
    __syncthreads();
    float inv = 1.0f / fmaxf(sqrtf(red[0] + red[1]), EPSF);
    float dot = 0.f;
    #pragma unroll 4
    for (int k4 = 0; k4 < D / 4; k4++) {
        float4 v = xs[k4];
        float4 w = g_kn4[k4 * R + tid];
        dot += v.x * w.x + v.y * w.y + v.z * w.z + v.w * w.w;
    }
    float csim = (dot * inv + 1.0f) * 0.5f;
    float s = warpSum(csim);
    if ((tid & 31) == 0) red2[tid >> 5] = s;
    __syncthreads();
    g_S[(size_t)row * R + tid] = csim / (red2[0] + red2[1]);
}

__global__ void k_f() {
    int br = blockIdx.x;
    int b = br >> 6, r = br & 63;
    int tid = threadIdx.x;
    float acc = 0.f;
    for (int n = tid; n < N; n += 256)
        acc += g_S[((size_t)(b * N + n)) * R + r];
    acc = warpSum(acc);
    __shared__ float red[8];
    if ((tid & 31) == 0) red[tid >> 5] = acc;
    __syncthreads();
    if (tid == 0) {
        float t = 0.f;
        #pragma unroll
        for (int i = 0; i < 8; i++) t += red[i];
        g_f[br] = t;
    }
}

__global__ void k_C(float* __restrict__ outC) {
    int gw = (blockIdx.x * blockDim.x + threadIdx.x) >> 5;
    if (gw >= B * N) return;
    int lane = threadIdx.x & 31;
    int row = gw, b = row >> 11;
    const float* Sr = &g_S[(size_t)row * R];
    float s0 = Sr[lane], s1 = Sr[lane + 32];
    float f0 = g_f[b * R + lane], f1 = g_f[b * R + lane + 32];
    float p0 = s0 * s0 / (f0 + EPSF), p1 = s1 * s1 / (f1 + EPSF);
    float ps = warpSum(p0 + p1);
    p0 /= (ps + EPSF); p1 /= (ps + EPSF);
    float kl = p0 * (logf(p0 + EPSF) - logf(s0 + EPSF))
             + p1 * (logf(p1 + EPSF) - logf(s1 + EPSF));
    kl = warpSum(kl);
    float mx = warpMax(fmaxf(s0, s1));
    float e0 = expf(s0 - mx), e1 = expf(s1 - mx);
    float es = warpSum(e0 + e1);
    float c0 = e0 / es, c1 = e1 / es;
    outC[(size_t)row * R + lane] = c0;
    outC[(size_t)row * R + lane + 32] = c1;
    float nrm = warpSum(c0 * c0 + c1 * c1);
    float invn = rsqrtf(nrm);
    g_Ch[(size_t)row * R + lane]      = __float2half_rn(c0 * invn);
    g_Ch[(size_t)row * R + lane + 32] = __float2half_rn(c1 * invn);
    if (lane == 0) g_kl[row] = kl * g_mask[row];
}

__global__ void k_loss(float* __restrict__ outLoss) {
    int tid = threadIdx.x;
    float a = 0.f, mm = 0.f;
    for (int i = tid; i < B * N; i += 256) { a += g_kl[i]; mm += g_mask[i]; }
    a = warpSum(a); mm = warpSum(mm);
    __shared__ float ra[8], rm[8];
    if ((tid & 31) == 0) { ra[tid >> 5] = a; rm[tid >> 5] = mm; }
    __syncthreads();
    if (tid == 0) {
        float A = 0.f, M = 0.f;
        #pragma unroll
        for (int i = 0; i < 8; i++) { A += ra[i]; M += rm[i]; }
        *outLoss = A / (M + EPSF);
    }
}

__global__ void k_seg(const void* __restrict__ seg, float* __restrict__ outSeg) {
    int i = blockIdx.x * blockDim.x + threadIdx.x;
    if (i < B * HW) outSeg[i] = (float)seg_at(seg, i, g_is64);
}

// ================= k_fused: out = rownorm(mask o Chat Chat^T) @ x =================
// CTA: 128 n-rows x full D=384. grid = B*16 = 128 (one wave). 512 threads.
// Loop m-chunks of 64: stage1 HMMA P = Cn @ Cm^T (mask + rowsum), stage2 acc += P @ x.
constexpr int OFF_CN  = 0;                       // 128 x 72 half   = 18432
constexpr int OFF_CM  = 18432;                   // 2 x 64 x 72     = 18432
constexpr int OFF_X   = 36864;                   // 2 x 384 x 72    = 110592
constexpr int OFF_P   = 147456;                  // 128 x 72        = 18432
constexpr int OFF_ADJ = 165888;                  // 256 u32         = 1024
constexpr int OFF_ROW = 166912;                  // 128 f32         = 512
constexpr int OFF_PART= 167424;                  // 4 x 128 f32     = 2048
constexpr int FUSED_SMEM = 169472;

__global__ void __launch_bounds__(512, 1) k_fused(float* __restrict__ out) {
    extern __shared__ char smem[];
    uint32_t sb = smem_u32(smem);
    int tid = threadIdx.x, wid = tid >> 5, lane = tid & 31;
    int gid = lane >> 2, tid4 = lane & 3;
    int mw = wid >> 2, nw = wid & 3;            // 4 x 4 warps
    int bid = blockIdx.x;
    int mt = bid & 15, b = bid >> 4;
    int n0 = mt * 128;

    __half*   sCn  = (__half*)(smem + OFF_CN);
    __half*   sP   = (__half*)(smem + OFF_P);
    uint32_t* sadj = (uint32_t*)(smem + OFF_ADJ);
    float*    srow = (float*)(smem + OFF_ROW);
    float*    spart= (float*)(smem + OFF_PART);

    // load Cn tile (plain) + zero partials
    #pragma unroll
    for (int i = 0; i < 2; i++) {
        int idx = tid + 512 * i;                // 0..1023
        int row = idx >> 3, sg = idx & 7;
        *(uint4*)(sCn + row * 72 + sg * 8) =
            *(const uint4*)(g_Ch + (size_t)(b * N + n0 + row) * R + sg * 8);
    }
    if (tid < 512) spart[tid] = 0.f;            // 4*128

    auto issue = [&](int c) {
        int buf = c & 1;
        uint32_t cmB = sb + OFF_CM + buf * 9216;
        uint32_t xB  = sb + OFF_X  + buf * 55296;
        {   // Cm chunk: 64 rows x 128B
            int row = tid >> 3, sg = tid & 7;
            cp16(cmB + row * 144 + sg * 16,
                 g_Ch + (size_t)(b * N + c * 64 + row) * R + sg * 8);
        }
        #pragma unroll
        for (int j = 0; j < 6; j++) {           // x^T chunk: 384 rows x 128B
            int idx = tid + 512 * j;
            int row = idx >> 3, sg = idx & 7;
            cp16(xB + row * 144 + sg * 16,
                 g_xT + (size_t)(b * D + row) * N + c * 64 + sg * 8);
        }
        CP_COMMIT();
    };

    float acc[2][12][4];
    #pragma unroll
    for (int mi = 0; mi < 2; mi++)
        #pragma unroll
        for (int ni = 0; ni < 12; ni++)
            #pragma unroll
            for (int q = 0; q < 4; q++) acc[mi][ni][q] = 0.f;
    float rs[4] = {0.f, 0.f, 0.f, 0.f};

    issue(0);

    for (int c = 0; c < 32; c++) {
        int buf = c & 1;
        CP_WAIT(0);
        __syncthreads();                        // chunk data ready; prev sP readers done
        if (c + 1 < 32) issue(c + 1);
        if (tid < 256)                          // adjacency words for this chunk
            sadj[tid] = g_adj[((size_t)(b * N + n0 + (tid >> 1)) << 6) + c * 2 + (tid & 1)];

        // ---- stage 1: P = Cn @ Cm^T (K = 64) ----
        const __half* bufCm = (const __half*)(smem + OFF_CM + buf * 9216);
        float p[2][2][4];
        #pragma unroll
        for (int mi = 0; mi < 2; mi++)
            #pragma unroll
            for (int ni = 0; ni < 2; ni++)
                #pragma unroll
                for (int q = 0; q < 4; q++) p[mi][ni][q] = 0.f;
        #pragma unroll
        for (int ks = 0; ks < 4; ks++) {
            int k0 = ks * 16 + tid4 * 2;
            uint32_t bf[2][2];
            #pragma unroll
            for (int ni = 0; ni < 2; ni++) {
                const __half* bp = bufCm + (nw * 16 + ni * 8 + gid) * 72 + k0;
                bf[ni][0] = *(const uint32_t*)bp;
                bf[ni][1] = *(const uint32_t*)(bp + 8);
            }
            #pragma unroll
            for (int mi = 0; mi < 2; mi++) {
                const __half* ap = sCn + (mw * 32 + mi * 16 + gid) * 72 + k0;
                uint32_t a0 = *(const uint32_t*)ap;
                uint32_t a2 = *(const uint32_t*)(ap + 8);
                uint32_t a1 = *(const uint32_t*)(ap + 8 * 72);
                uint32_t a3 = *(const uint32_t*)(ap + 8 * 72 + 8);
                #pragma unroll
                for (int ni = 0; ni < 2; ni++)
                    mma16816(p[mi][ni], a0, a1, a2, a3, bf[ni][0], bf[ni][1]);
            }
        }
        __syncthreads();                        // sadj visible

        // ---- stage 1 epilogue: mask, rowsum, fp16 -> sP ----
        #pragma unroll
        for (int mi = 0; mi < 2; mi++)
            #pragma unroll
            for (int h = 0; h < 2; h++) {
                int r = mw * 32 + mi * 16 + gid + 8 * h;
                uint32_t w0 = sadj[r * 2], w1 = sadj[r * 2 + 1];
                #pragma unroll
                for (int ni = 0; ni < 2; ni++) {
                    int cc = nw * 16 + ni * 8 + tid4 * 2;
                    uint32_t word = (cc < 32) ? w0 : w1;
                    int sh = cc & 31;
                    float v0 = ((word >> sh) & 1u) ? p[mi][ni][2 * h + 0] : 0.f;
                    float v1 = ((word >> (sh + 1)) & 1u) ? p[mi][ni][2 * h + 1] : 0.f;
                    rs[mi * 2 + h] += v0 + v1;
                    *(__half2*)(sP + r * 72 + cc) = __floats2half2_rn(v0, v1);
                }
            }
        __syncthreads();                        // sP ready

        // ---- stage 2: acc += P @ x_chunk (K = 64) ----
        const __half* bufX = (const __half*)(smem + OFF_X + buf * 55296);
        #pragma unroll
        for (int ks = 0; ks < 4; ks++) {
            int k0 = ks * 16 + tid4 * 2;
            uint32_t a[2][4];
            #pragma unroll
            for (int mi = 0; mi < 2; mi++) {
                const __half* ap = sP + (mw * 32 + mi * 16 + gid) * 72 + k0;
                a[mi][0] = *(const uint32_t*)ap;
                a[mi][2] = *(const uint32_t*)(ap + 8);
                a[mi][1] = *(const uint32_t*)(ap + 8 * 72);
                a[mi][3] = *(const uint32_t*)(ap + 8 * 72 + 8);
            }
            #pragma unroll
            for (int ni = 0; ni < 12; ni++) {
                const __half* bp = bufX + (nw * 96 + ni * 8 + gid) * 72 + k0;
                uint32_t b0 = *(const uint32_t*)bp;
                uint32_t b1 = *(const uint32_t*)(bp + 8);
                mma16816(acc[0][ni], a[0][0], a[0][1], a[0][2], a[0][3], b0, b1);
                mma16816(acc[1][ni], a[1][0], a[1][1], a[1][2], a[1][3], b0, b1);
            }
        }
    }

    // ---- deterministic rowsum reduction ----
    #pragma unroll
    for (int q = 0; q < 4; q++) {
        rs[q] += __shfl_xor_sync(0xffffffffu, rs[q], 1);
        rs[q] += __shfl_xor_sync(0xffffffffu, rs[q], 2);
    }
    if (tid4 == 0) {
        #pragma unroll
        for (int mi = 0; mi < 2; mi++)
            #pragma unroll
            for (int h = 0; h < 2; h++)
                spart[nw * 128 + mw * 32 + mi * 16 + gid + 8 * h] = rs[mi * 2 + h];
    }
    __syncthreads();
    if (tid < 128) {
        float s = spart[tid] + spart[128 + tid] + spart[256 + tid] + spart[384 + tid];
        srow[tid] = 1.0f / (s + EPSF);
    }
    __syncthreads();

    // ---- epilogue ----
    #pragma unroll
    for (int mi = 0; mi < 2; mi++)
        #pragma unroll
        for (int h = 0; h < 2; h++) {
            int r = mw * 32 + mi * 16 + gid + 8 * h;
            float inv = srow[r];
            float* base = out + (size_t)(b * N + n0 + r) * D;
            #pragma unroll
            for (int ni = 0; ni < 12; ni++) {
                int d = nw * 96 + ni * 8 + tid4 * 2;
                *(float2*)(base + d) = make_float2(acc[mi][ni][2 * h] * inv,
                                                   acc[mi][ni][2 * h + 1] * inv);
            }
        }
}

// ---------------- launch ----------------
extern "C" void kernel_launch(void* const* d_in, const int* in_sizes, int n_in,
                              void* d_out, int out_size) {
    const float* x      = (const float*)d_in[0];
    const void*  seg    = d_in[1];
    const float* protos = (const float*)d_in[2];
    float* out = (float*)d_out;

    float* outSeg  = out + SEG_OFF;
    float* outLoss = out + LOSS_OFF;
    float* outC    = out + C_OFF;

    cudaFuncSetAttribute(k_fused, cudaFuncAttributeMaxDynamicSharedMemorySize, FUSED_SMEM);

    k_detect<<<1, 32>>>((const unsigned int*)seg);
    k_init<<<(B * N * W64) / 256, 256>>>();
    k_adj<<<(B * HW) / 256, 256>>>(seg);
    k_kn<<<R, 128>>>(protos);
    k_xT<<<dim3(N / 32, D / 32, B), dim3(32, 8)>>>(x);
    k_S<<<B * N, 64>>>(x);
    k_f<<<B * R, 256>>>();
    k_C<<<(B * N) / 4, 128>>>(outC);
    k_loss<<<1, 256>>>(outLoss);
    k_seg<<<(B * HW) / 256, 256>>>(seg, outSeg);
    k_fused<<<B * 16, 512, FUSED_SMEM>>>(out);
}

// round 8
// speedup vs baseline: 1.4406x; 1.0572x over previous
#include <cuda_runtime.h>
#include <cuda_fp16.h>
#include <stdint.h>

#define EPSF 1e-8f

constexpr int B = 8, N = 2048, D = 384, R = 64;
constexpr int HW = 256 * 256;
constexpr int W64 = N / 32;

// Output layout (float32, concatenated in reference return order)
constexpr size_t SEG_OFF  = (size_t)B * N * D;        // 6291456
constexpr size_t LOSS_OFF = SEG_OFF + (size_t)B * HW; // 6815744
constexpr size_t C_OFF    = LOSS_OFF + 1;             // 6815745

// ---------------- device scratch ----------------
__device__ uint32_t g_adj[(size_t)B * N * W64];   // 4 MB bitmask adjacency
__device__ float    g_S  [(size_t)B * N * R];     // 4 MB
__device__ __half   g_Ch [(size_t)B * N * R];     // 2 MB normalized Chat fp16
__device__ __half   g_xT [(size_t)B * D * N];     // 12.6 MB x^T fp16
__device__ float4   g_kn4[(D / 4) * R];
__device__ float    g_mask[B * N];
__device__ float    g_f  [B * R];
__device__ float    g_kl [B * N];
__device__ int      g_is64;

// ---------------- helpers ----------------
__device__ __forceinline__ float warpSum(float v) {
    #pragma unroll
    for (int o = 16; o; o >>= 1) v += __shfl_xor_sync(0xffffffffu, v, o);
    return v;
}
__device__ __forceinline__ float warpMax(float v) {
    #pragma unroll
    for (int o = 16; o; o >>= 1) v = fmaxf(v, __shfl_xor_sync(0xffffffffu, v, o));
    return v;
}
__device__ __forceinline__ int seg_at(const void* seg, int idx, int is64) {
    if (is64) return (int)((const long long*)seg)[idx];
    return ((const int*)seg)[idx];
}
__device__ __forceinline__ uint32_t smem_u32(const void* p) {
    uint32_t a;
    asm("{ .reg .u64 t; cvta.to.shared.u64 t, %1; cvt.u32.u64 %0, t; }" : "=r"(a) : "l"(p));
    return a;
}
__device__ __forceinline__ void cp16(uint32_t saddr, const void* g) {
    asm volatile("cp.async.cg.shared.global [%0], [%1], 16;" :: "r"(saddr), "l"(g));
}
#define CP_COMMIT() asm volatile("cp.async.commit_group;" ::: "memory")
#define CP_WAIT(n)  asm volatile("cp.async.wait_group %0;" :: "n"(n) : "memory")

__device__ __forceinline__ void mma16816(float* c, uint32_t a0, uint32_t a1,
                                         uint32_t a2, uint32_t a3,
                                         uint32_t b0, uint32_t b1) {
    asm volatile(
        "mma.sync.aligned.m16n8k16.row.col.f32.f16.f16.f32 "
        "{%0,%1,%2,%3}, {%4,%5,%6,%7}, {%8,%9}, {%0,%1,%2,%3};\n"
        : "+f"(c[0]), "+f"(c[1]), "+f"(c[2]), "+f"(c[3])
        : "r"(a0), "r"(a1), "r"(a2), "r"(a3), "r"(b0), "r"(b1));
}
__device__ __forceinline__ void ldsm4(uint32_t& r0, uint32_t& r1, uint32_t& r2,
                                      uint32_t& r3, uint32_t a) {
    asm volatile("ldmatrix.sync.aligned.m8n8.x4.shared.b16 {%0,%1,%2,%3}, [%4];"
                 : "=r"(r0), "=r"(r1), "=r"(r2), "=r"(r3) : "r"(a));
}

// ================= small kernels =================
__global__ void k_detect(const unsigned int* __restrict__ seg) {
    if (blockIdx.x == 0 && threadIdx.x == 0) {
        unsigned int acc = 0;
        for (int i = 0; i < 128; i++) acc |= seg[2 * i + 1];
        g_is64 = (acc == 0u) ? 1 : 0;
    }
}

__global__ void k_init() {
    int idx = blockIdx.x * blockDim.x + threadIdx.x;  // B*N*W64
    int row = idx >> 6, w = idx & 63, n = row & (N - 1);
    g_adj[idx] = (w == (n >> 5)) ? (1u << (n & 31)) : 0u;
    if (idx < B * N) g_mask[idx] = 0.0f;
    if (idx < B * R) g_f[idx] = 0.0f;
}

__global__ void k_adj(const void* __restrict__ seg) {
    int idx = blockIdx.x * blockDim.x + threadIdx.x;
    if (idx >= B * HW) return;
    int is64 = g_is64;
    int b = idx >> 16, p = idx & 65535;
    int yy = p >> 8, xx = p & 255;
    int s = seg_at(seg, idx, is64);
    g_mask[b * N + s] = 1.0f;
    if (xx < 255) {
        int t = seg_at(seg, idx + 1, is64);
        if (s != t && s != 0 && t != 0) {
            atomicOr(&g_adj[((size_t)(b * N + s) << 6) + (t >> 5)], 1u << (t & 31));
            atomicOr(&g_adj[((size_t)(b * N + t) << 6) + (s >> 5)], 1u << (s & 31));
        }
    }
    if (yy < 255) {
        int t = seg_at(seg, idx + 256, is64);
        if (s != t && s != 0 && t != 0) {
            atomicOr(&g_adj[((size_t)(b * N + s) << 6) + (t >> 5)], 1u << (t & 31));
            atomicOr(&g_adj[((size_t)(b * N + t) << 6) + (s >> 5)], 1u << (s & 31));
        }
    }
}

__global__ void k_kn(const float* __restrict__ protos) {
    int r = blockIdx.x, tid = threadIdx.x;
    __shared__ float red[4];
    float ss = 0.f;
    for (int k = tid; k < D; k += 128) { float v = protos[r * D + k]; ss += v * v; }
    ss = warpSum(ss);
    if ((tid & 31) == 0) red[tid >> 5] = ss;
    __syncthreads();
    float inv = 1.0f / fmaxf(sqrtf(red[0] + red[1] + red[2] + red[3]), EPSF);
    for (int k4 = tid; k4 < D / 4; k4 += 128) {
        float4 v;
        v.x = protos[r * D + 4 * k4 + 0] * inv;
        v.y = protos[r * D + 4 * k4 + 1] * inv;
        v.z = protos[r * D + 4 * k4 + 2] * inv;
        v.w = protos[r * D + 4 * k4 + 3] * inv;
        g_kn4[k4 * R + r] = v;
    }
}

// x[b][n][d] -> g_xT[b][d][n] fp16
__global__ void k_xT(const float* __restrict__ x) {
    __shared__ float ts[32][33];
    int b = blockIdx.z, ntile = blockIdx.x, dtile = blockIdx.y;
    int tx = threadIdx.x, ty = threadIdx.y;  // 32 x 8
    #pragma unroll
    for (int i = 0; i < 4; i++) {
        int n = ntile * 32 + ty + 8 * i;
        ts[ty + 8 * i][tx] = x[((size_t)(b * N + n)) * D + dtile * 32 + tx];
    }
    __syncthreads();
    #pragma unroll
    for (int i = 0; i < 4; i++) {
        int d = dtile * 32 + ty + 8 * i;
        g_xT[((size_t)(b * D + d)) * N + ntile * 32 + tx] = __float2half_rn(ts[tx][ty + 8 * i]);
    }
}

__global__ void __launch_bounds__(64) k_S(const float* __restrict__ x) {
    int row = blockIdx.x, tid = threadIdx.x;
    __shared__ float4 xs[D / 4];
    __shared__ float red[2], red2[2];
    float ss = 0.f;
    const float4* xr = (const float4*)(x + (size_t)row * D);
    for (int k4 = tid; k4 < D / 4; k4 += 64) {
        float4 v = xr[k4];
        xs[k4] = v;
        ss += v.x * v.x + v.y * v.y + v.z * v.z + v.w * v.w;
    }
    ss = warpSum(ss);
    if ((tid & 31) == 0) red[tid >> 5] = ss;
    __syncthreads();
    float inv = 1.0f / fmaxf(sqrtf(red[0] + red[1]), EPSF);
    float dot = 0.f;
    #pragma unroll 4
    for (int k4 = 0; k4 < D / 4; k4++) {
        float4 v = xs[k4];
        float4 w = g_kn4[k4 * R + tid];
        dot += v.x * w.x + v.y * w.y + v.z * w.z + v.w * w.w;
    }
    float csim = (dot * inv + 1.0f) * 0.5f;
    float s = warpSum(csim);
    if ((tid & 31) == 0) red2[tid >> 5] = s;
    __syncthreads();
    g_S[(size_t)row * R + tid] = csim / (red2[0] + red2[1]);
}

__global__ void k_f() {
    int br = blockIdx.x;
    int b = br >> 6, r = br & 63;
    int tid = threadIdx.x;
    float acc = 0.f;
    for (int n = tid; n < N; n += 256)
        acc += g_S[((size_t)(b * N + n)) * R + r];
    acc = warpSum(acc);
    __shared__ float red[8];
    if ((tid & 31) == 0) red[tid >> 5] = acc;
    __syncthreads();
    if (tid == 0) {
        float t = 0.f;
        #pragma unroll
        for (int i = 0; i < 8; i++) t += red[i];
        g_f[br] = t;
    }
}

__global__ void k_C(float* __restrict__ outC) {
    int gw = (blockIdx.x * blockDim.x + threadIdx.x) >> 5;
    if (gw >= B * N) return;
    int lane = threadIdx.x & 31;
    int row = gw, b = row >> 11;
    const float* Sr = &g_S[(size_t)row * R];
    float s0 = Sr[lane], s1 = Sr[lane + 32];
    float f0 = g_f[b * R + lane], f1 = g_f[b * R + lane + 32];
    float p0 = s0 * s0 / (f0 + EPSF), p1 = s1 * s1 / (f1 + EPSF);
    float ps = warpSum(p0 + p1);
    p0 /= (ps + EPSF); p1 /= (ps + EPSF);
    float kl = p0 * (logf(p0 + EPSF) - logf(s0 + EPSF))
             + p1 * (logf(p1 + EPSF) - logf(s1 + EPSF));
    kl = warpSum(kl);
    float mx = warpMax(fmaxf(s0, s1));
    float e0 = expf(s0 - mx), e1 = expf(s1 - mx);
    float es = warpSum(e0 + e1);
    float c0 = e0 / es, c1 = e1 / es;
    outC[(size_t)row * R + lane] = c0;
    outC[(size_t)row * R + lane + 32] = c1;
    float nrm = warpSum(c0 * c0 + c1 * c1);
    float invn = rsqrtf(nrm);
    g_Ch[(size_t)row * R + lane]      = __float2half_rn(c0 * invn);
    g_Ch[(size_t)row * R + lane + 32] = __float2half_rn(c1 * invn);
    if (lane == 0) g_kl[row] = kl * g_mask[row];
}

__global__ void k_loss(float* __restrict__ outLoss) {
    int tid = threadIdx.x;
    float a = 0.f, mm = 0.f;
    for (int i = tid; i < B * N; i += 256) { a += g_kl[i]; mm += g_mask[i]; }
    a = warpSum(a); mm = warpSum(mm);
    __shared__ float ra[8], rm[8];
    if ((tid & 31) == 0) { ra[tid >> 5] = a; rm[tid >> 5] = mm; }
    __syncthreads();
    if (tid == 0) {
        float A = 0.f, M = 0.f;
        #pragma unroll
        for (int i = 0; i < 8; i++) { A += ra[i]; M += rm[i]; }
        *outLoss = A / (M + EPSF);
    }
}

__global__ void k_seg(const void* __restrict__ seg, float* __restrict__ outSeg) {
    int i = blockIdx.x * blockDim.x + threadIdx.x;
    if (i < B * HW) outSeg[i] = (float)seg_at(seg, i, g_is64);
}

// ================= k_fused: out = rownorm(mask o Chat Chat^T) @ x =================
// CTA: 128 n-rows x full D=384. grid = B*16 = 128 (one wave). 512 threads.
// Loop m-chunks of 64: stage1 HMMA P = Cn @ Cm^T (mask + rowsum), stage2 acc += P @ x.
// All fragment loads via ldmatrix (x4).
constexpr int OFF_CN  = 0;                       // 128 x 72 half   = 18432
constexpr int OFF_CM  = 18432;                   // 2 x 64 x 72     = 18432
constexpr int OFF_X   = 36864;                   // 2 x 384 x 72    = 110592
constexpr int OFF_P   = 147456;                  // 128 x 72        = 18432
constexpr int OFF_ADJ = 165888;                  // 256 u32         = 1024
constexpr int OFF_ROW = 166912;                  // 128 f32         = 512
constexpr int OFF_PART= 167424;                  // 4 x 128 f32     = 2048
constexpr int FUSED_SMEM = 169472;

__global__ void __launch_bounds__(512, 1) k_fused(float* __restrict__ out) {
    extern __shared__ char smem[];
    uint32_t sb = smem_u32(smem);
    int tid = threadIdx.x, wid = tid >> 5, lane = tid & 31;
    int gid = lane >> 2, tid4 = lane & 3;
    int mw = wid >> 2, nw = wid & 3;            // 4 x 4 warps
    int bid = blockIdx.x;
    int mt = bid & 15, b = bid >> 4;
    int n0 = mt * 128;

    __half*   sCn  = (__half*)(smem + OFF_CN);
    __half*   sP   = (__half*)(smem + OFF_P);
    uint32_t* sadj = (uint32_t*)(smem + OFF_ADJ);
    float*    srow = (float*)(smem + OFF_ROW);
    float*    spart= (float*)(smem + OFF_PART);

    // per-lane ldmatrix offsets (bytes) within a tile base
    // A-type (16x16): rows lane&15, col half +8 if lane>=16
    uint32_t aoff = (uint32_t)(lane & 15) * 144 + ((lane >> 4) & 1) * 16;
    // B-type (two 8-row n-tiles x k16): row (lane&7) + 8*(lane>=16), col +8 halves if bit3
    uint32_t boff = ((uint32_t)((lane & 7) + ((lane >> 4) & 1) * 8)) * 144
                  + ((lane >> 3) & 1) * 16;

    // load Cn tile
    #pragma unroll
    for (int i = 0; i < 2; i++) {
        int idx = tid + 512 * i;                // 0..1023
        int row = idx >> 3, sg = idx & 7;
        *(uint4*)(sCn + row * 72 + sg * 8) =
            *(const uint4*)(g_Ch + (size_t)(b * N + n0 + row) * R + sg * 8);
    }

    auto issue = [&](int c) {
        int buf = c & 1;
        uint32_t cmB = sb + OFF_CM + buf * 9216;
        uint32_t xB  = sb + OFF_X  + buf * 55296;
        {   // Cm chunk: 64 rows x 128B
            int row = tid >> 3, sg = tid & 7;
            cp16(cmB + row * 144 + sg * 16,
                 g_Ch + (size_t)(b * N + c * 64 + row) * R + sg * 8);
        }
        #pragma unroll
        for (int j = 0; j < 6; j++) {           // x^T chunk: 384 rows x 128B
            int idx = tid + 512 * j;
            int row = idx >> 3, sg = idx & 7;
            cp16(xB + row * 144 + sg * 16,
                 g_xT + (size_t)(b * D + row) * N + c * 64 + sg * 8);
        }
        CP_COMMIT();
    };

    float acc[2][12][4];
    #pragma unroll
    for (int mi = 0; mi < 2; mi++)
        #pragma unroll
        for (int ni = 0; ni < 12; ni++)
            #pragma unroll
            for (int q = 0; q < 4; q++) acc[mi][ni][q] = 0.f;
    float rs[4] = {0.f, 0.f, 0.f, 0.f};

    // fixed smem fragment bases
    uint32_t aCn0 = sb + OFF_CN + (mw * 32) * 144 + aoff;           // + mi*16*144 + k0*2
    uint32_t aP0  = sb + OFF_P  + (mw * 32) * 144 + aoff;
    issue(0);

    for (int c = 0; c < 32; c++) {
        int buf = c & 1;
        CP_WAIT(0);
        __syncthreads();                        // chunk data ready; prev sP readers done
        if (c + 1 < 32) issue(c + 1);
        if (tid < 256)                          // adjacency words for this chunk
            sadj[tid] = g_adj[((size_t)(b * N + n0 + (tid >> 1)) << 6) + c * 2 + (tid & 1)];

        // ---- stage 1: P = Cn @ Cm^T (K = 64) ----
        uint32_t bCm = sb + OFF_CM + buf * 9216 + (nw * 16) * 144 + boff;
        float p[2][2][4];
        #pragma unroll
        for (int mi = 0; mi < 2; mi++)
            #pragma unroll
            for (int ni = 0; ni < 2; ni++)
                #pragma unroll
                for (int q = 0; q < 4; q++) p[mi][ni][q] = 0.f;
        #pragma unroll
        for (int ks = 0; ks < 4; ks++) {
            uint32_t k2 = ks * 32;              // k0*2 bytes
            uint32_t b00, b01, b10, b11;
            ldsm4(b00, b01, b10, b11, bCm + k2);
            #pragma unroll
            for (int mi = 0; mi < 2; mi++) {
                uint32_t a0, a1, a2, a3;
                ldsm4(a0, a1, a2, a3, aCn0 + mi * (16 * 144) + k2);
                mma16816(p[mi][0], a0, a1, a2, a3, b00, b01);
                mma16816(p[mi][1], a0, a1, a2, a3, b10, b11);
            }
        }
        __syncthreads();                        // sadj visible

        // ---- stage 1 epilogue: mask, rowsum, fp16 -> sP ----
        #pragma unroll
        for (int mi = 0; mi < 2; mi++)
            #pragma unroll
            for (int h = 0; h < 2; h++) {
                int r = mw * 32 + mi * 16 + gid + 8 * h;
                uint32_t w0 = sadj[r * 2], w1 = sadj[r * 2 + 1];
                #pragma unroll
                for (int ni = 0; ni < 2; ni++) {
                    int cc = nw * 16 + ni * 8 + tid4 * 2;
                    uint32_t word = (cc < 32) ? w0 : w1;
                    int sh = cc & 31;
                    float v0 = ((word >> sh) & 1u) ? p[mi][ni][2 * h + 0] : 0.f;
                    float v1 = ((word >> (sh + 1)) & 1u) ? p[mi][ni][2 * h + 1] : 0.f;
                    rs[mi * 2 + h] += v0 + v1;
                    *(__half2*)(sP + r * 72 + cc) = __floats2half2_rn(v0, v1);
                }
            }
        __syncthreads();                        // sP ready

        // ---- stage 2: acc += P @ x_chunk (K = 64) ----
        uint32_t bX = sb + OFF_X + buf * 55296 + (nw * 96) * 144 + boff;
        #pragma unroll
        for (int ks = 0; ks < 4; ks++) {
            uint32_t k2 = ks * 32;
            uint32_t a[2][4];
            ldsm4(a[0][0], a[0][1], a[0][2], a[0][3], aP0 + k2);
            ldsm4(a[1][0], a[1][1], a[1][2], a[1][3], aP0 + 16 * 144 + k2);
            #pragma unroll
            for (int nj = 0; nj < 6; nj++) {
                uint32_t b00, b01, b10, b11;
                ldsm4(b00, b01, b10, b11, bX + nj * (16 * 144) + k2);
                mma16816(acc[0][2 * nj],     a[0][0], a[0][1], a[0][2], a[0][3], b00, b01);
                mma16816(acc[1][2 * nj],     a[1][0], a[1][1], a[1][2], a[1][3], b00, b01);
                mma16816(acc[0][2 * nj + 1], a[0][0], a[0][1], a[0][2], a[0][3], b10, b11);
                mma16816(acc[1][2 * nj + 1], a[1][0], a[1][1], a[1][2], a[1][3], b10, b11);
            }
        }
    }

    // ---- deterministic rowsum reduction ----
    #pragma unroll
    for (int q = 0; q < 4; q++) {
        rs[q] += __shfl_xor_sync(0xffffffffu, rs[q], 1);
        rs[q] += __shfl_xor_sync(0xffffffffu, rs[q], 2);
    }
    if (tid4 == 0) {
        #pragma unroll
        for (int mi = 0; mi < 2; mi++)
            #pragma unroll
            for (int h = 0; h < 2; h++)
                spart[nw * 128 + mw * 32 + mi * 16 + gid + 8 * h] = rs[mi * 2 + h];
    }
    __syncthreads();
    if (tid < 128) {
        float s = spart[tid] + spart[128 + tid] + spart[256 + tid] + spart[384 + tid];
        srow[tid] = 1.0f / (s + EPSF);
    }
    __syncthreads();

    // ---- epilogue ----
    #pragma unroll
    for (int mi = 0; mi < 2; mi++)
        #pragma unroll
        for (int h = 0; h < 2; h++) {
            int r = mw * 32 + mi * 16 + gid + 8 * h;
            float inv = srow[r];
            float* base = out + (size_t)(b * N + n0 + r) * D;
            #pragma unroll
            for (int ni = 0; ni < 12; ni++) {
                int d = nw * 96 + ni * 8 + tid4 * 2;
                *(float2*)(base + d) = make_float2(acc[mi][ni][2 * h] * inv,
                                                   acc[mi][ni][2 * h + 1] * inv);
            }
        }
}

// ---------------- launch ----------------
extern "C" void kernel_launch(void* const* d_in, const int* in_sizes, int n_in,
                              void* d_out, int out_size) {
    const float* x      = (const float*)d_in[0];
    const void*  seg    = d_in[1];
    const float* protos = (const float*)d_in[2];
    float* out = (float*)d_out;

    float* outSeg  = out + SEG_OFF;
    float* outLoss = out + LOSS_OFF;
    float* outC    = out + C_OFF;

    cudaFuncSetAttribute(k_fused, cudaFuncAttributeMaxDynamicSharedMemorySize, FUSED_SMEM);

    k_detect<<<1, 32>>>((const unsigned int*)seg);
    k_init<<<(B * N * W64) / 256, 256>>>();
    k_adj<<<(B * HW) / 256, 256>>>(seg);
    k_kn<<<R, 128>>>(protos);
    k_xT<<<dim3(N / 32, D / 32, B), dim3(32, 8)>>>(x);
    k_S<<<B * N, 64>>>(x);
    k_f<<<B * R, 256>>>();
    k_C<<<(B * N) / 4, 128>>>(outC);
    k_loss<<<1, 256>>>(outLoss);
    k_seg<<<(B * HW) / 256, 256>>>(seg, outSeg);
    k_fused<<<B * 16, 512, FUSED_SMEM>>>(out);
}